// round 13
// baseline (speedup 1.0000x reference)
#include <cuda_runtime.h>
#include <math.h>

#define BDIM 16
#define SDIM 2048
#define IDIM 1024
#define HDIM 1024
#define NBLK 128   // GRU persistent blocks (1 per SM, 8 hidden cols each)

// Scratch (static __device__ — runtime allocation is forbidden)
__device__ float g_gi[(size_t)BDIM * SDIM * 3 * HDIM];   // [B,S,3H]
__device__ float g_rnn[(size_t)BDIM * SDIM * HDIM];      // [B,S,H]
__device__ float g_hT[2 * HDIM * BDIM];                  // transposed h, double-buffered [buf][k][b]

// grid barrier state (self-resetting across graph replays)
__device__ unsigned g_count = 0;
__device__ volatile unsigned g_gen = 0;

// ---------------------------------------------------------------------------
// f32x2 packed-math helpers (sm_100+)
// ---------------------------------------------------------------------------
__device__ __forceinline__ unsigned long long dup2(float x) {
    unsigned long long r;
    asm("mov.b64 %0, {%1, %1};" : "=l"(r) : "f"(x));
    return r;
}
__device__ __forceinline__ float2 unpack2(unsigned long long v) {
    float2 f;
    asm("mov.b64 {%0, %1}, %2;" : "=f"(f.x), "=f"(f.y) : "l"(v));
    return f;
}
#define FMA2(d, a, b) asm("fma.rn.f32x2 %0, %1, %2, %0;" : "+l"(d) : "l"(a), "l"(b))
#define ADD2(d, a)    asm("add.rn.f32x2 %0, %0, %1;"     : "+l"(d) : "l"(a))

// ---------------------------------------------------------------------------
// NT SGEMM (f32x2), BK=8, double-buffered smem + 8-reg prefetch:
//   C[m,n] = sum_k A[m,k] * W[n,k] + bias[n]
// 128x128 tile, 256 threads, 8x8 per thread (as 8x4 f32x2).
// Per stage each thread holds only 2 float4 (A+W) -> no spill at 128-reg cap.
// One __syncthreads per 8-k stage; next stage's LDG issued before compute.
// Load mapping (row = tid>>1, half = tid&1): adjacent lanes cover a full 32B
// sector; each 128B line serves 4 consecutive stages via L1 hits.
// ---------------------------------------------------------------------------
__global__ void __launch_bounds__(256, 2) sgemm_nt(
    const float* __restrict__ A, const float* __restrict__ W,
    const float* __restrict__ bias, float* __restrict__ C,
    int M, int N, int K)
{
    __shared__ float As[2][8][128];
    __shared__ float Bs[2][8][128];

    const int tid = threadIdx.x;
    const int bm = blockIdx.y * 128;
    const int bn = blockIdx.x * 128;
    const int tx = tid & 15;
    const int ty = tid >> 4;

    const int lr = tid >> 1;        // row 0..127
    const int hf = tid & 1;         // k-half within stage (0: k0..3, 1: k4..7)

    const float* Ap = A + (size_t)(bm + lr) * K + hf * 4;
    const float* Wp = W + (size_t)(bn + lr) * K + hf * 4;

    unsigned long long acc[8][4];
#pragma unroll
    for (int i = 0; i < 8; i++)
#pragma unroll
        for (int j = 0; j < 4; j++) acc[i][j] = 0ull;

    // prologue: stage 0
    {
        float4 a0 = *(const float4*)(Ap);
        float4 w0 = *(const float4*)(Wp);
        As[0][hf * 4 + 0][lr] = a0.x; As[0][hf * 4 + 1][lr] = a0.y;
        As[0][hf * 4 + 2][lr] = a0.z; As[0][hf * 4 + 3][lr] = a0.w;
        Bs[0][hf * 4 + 0][lr] = w0.x; Bs[0][hf * 4 + 1][lr] = w0.y;
        Bs[0][hf * 4 + 2][lr] = w0.z; Bs[0][hf * 4 + 3][lr] = w0.w;
    }
    __syncthreads();

    const int NS = K / 8;
    for (int s = 0; s < NS; s++) {
        // prefetch next stage (8 held regs; latency hidden by compute)
        float4 an, wn;
        const bool more = (s + 1 < NS);
        if (more) {
            an = *(const float4*)(Ap + (s + 1) * 8);
            wn = *(const float4*)(Wp + (s + 1) * 8);
        }

        const int b = s & 1;
#pragma unroll
        for (int k = 0; k < 8; k++) {
            float a8[8];
            *(float4*)&a8[0] = *(const float4*)&As[b][k][ty * 8];
            *(float4*)&a8[4] = *(const float4*)&As[b][k][ty * 8 + 4];
            unsigned long long bp[4];
            {
                ulonglong2 t0 = *(const ulonglong2*)&Bs[b][k][tx * 8];
                ulonglong2 t1 = *(const ulonglong2*)&Bs[b][k][tx * 8 + 4];
                bp[0] = t0.x; bp[1] = t0.y; bp[2] = t1.x; bp[3] = t1.y;
            }
            unsigned long long ad[8];
#pragma unroll
            for (int i = 0; i < 8; i++) ad[i] = dup2(a8[i]);
#pragma unroll
            for (int i = 0; i < 8; i++)
#pragma unroll
                for (int j = 0; j < 4; j++)
                    FMA2(acc[i][j], ad[i], bp[j]);
        }

        if (more) {
            const int nb = b ^ 1;   // other buffer: fully consumed at stage s-1
            As[nb][hf * 4 + 0][lr] = an.x; As[nb][hf * 4 + 1][lr] = an.y;
            As[nb][hf * 4 + 2][lr] = an.z; As[nb][hf * 4 + 3][lr] = an.w;
            Bs[nb][hf * 4 + 0][lr] = wn.x; Bs[nb][hf * 4 + 1][lr] = wn.y;
            Bs[nb][hf * 4 + 2][lr] = wn.z; Bs[nb][hf * 4 + 3][lr] = wn.w;
        }
        __syncthreads();
    }

#pragma unroll
    for (int i = 0; i < 8; i++) {
        size_t row = (size_t)(bm + ty * 8 + i);
#pragma unroll
        for (int j = 0; j < 4; j++) {
            float2 f = unpack2(acc[i][j]);
            int n = bn + tx * 8 + 2 * j;
            float2 v;
            v.x = f.x + bias[n];
            v.y = f.y + bias[n + 1];
            *(float2*)&C[row * N + n] = v;
        }
    }
}

// ---------------------------------------------------------------------------
// Persistent GRU — EXACT R4/R12 version (best measured).
// 128 blocks x 256 threads; block owns 8 hidden cols.
// ---------------------------------------------------------------------------
__device__ __forceinline__ void gsync() {
    __syncthreads();
    if (threadIdx.x == 0) {
        unsigned gen = g_gen;
        __threadfence();
        if (atomicAdd(&g_count, 1u) == NBLK - 1u) {
            g_count = 0;
            __threadfence();
            g_gen = gen + 1;
        } else {
            while (g_gen == gen) {}
            __threadfence();
        }
    }
    __syncthreads();
}

#define HROW 20            // floats per h_s row (16 used + 4 pad -> conflict-free LDS.128)
#define SM_W   (24 * 1024)                 // floats
#define SM_H   (1024 * HROW)               // floats
#define SM_RED 192                         // ull (f32x2) entries

__global__ void __launch_bounds__(256, 1) gru_persistent(
    const float* __restrict__ gi, const float* __restrict__ w_hh,
    const float* __restrict__ b_hh, float* __restrict__ rnn,
    float* __restrict__ hT)
{
    extern __shared__ float sm[];
    float* w_s = sm;
    float* h_s = sm + SM_W;
    unsigned long long* red_s = (unsigned long long*)(sm + SM_W + SM_H);

    const int tid = threadIdx.x;
    const int bx = blockIdx.x;
    const int cg = tid >> 6;      // 0..3 column group
    const int ks = tid & 63;      // k slice

    // --- load own w_hh rows into smem (once) ---
    for (int idx = tid; idx < 24 * 256; idx += 256) {
        int lr = idx >> 8;
        int k4 = idx & 255;
        int g = lr >> 3, jl = lr & 7;
        float4 v = *(const float4*)(w_hh + ((size_t)(g * 1024 + bx * 8 + jl)) * 1024 + k4 * 4);
        *(float4*)(w_s + lr * 1024 + k4 * 4) = v;
    }

    // combine-thread constants
    const int jl_c = tid >> 4, b_c = tid & 15;
    const int col_c = bx * 8 + jl_c;
    float bh0 = 0.f, bh1 = 0.f, bh2 = 0.f;
    if (tid < 128) {
        bh0 = b_hh[col_c];
        bh1 = b_hh[1024 + col_c];
        bh2 = b_hh[2048 + col_c];
    }

    // per-thread w pointers (invariant across steps): c = jsub*3 + g
    const int j0 = cg * 2;
    const float* wc[6];
#pragma unroll
    for (int jsub = 0; jsub < 2; jsub++)
#pragma unroll
        for (int g = 0; g < 3; g++)
            wc[jsub * 3 + g] = w_s + (g * 8 + j0 + jsub) * 1024 + ks;

    __syncthreads();

    for (int t = 0; t < SDIM; t++) {
        // --- stage h_{t-1} into h_s[k][b] ---
        if (t == 0) {
            float4 z4 = make_float4(0.f, 0.f, 0.f, 0.f);
            for (int r = tid; r < SM_H / 4; r += 256)
                ((float4*)h_s)[r] = z4;
        } else {
            const size_t hoff = (size_t)((t - 1) & 1) * (HDIM * BDIM);
            for (int r = tid; r < 4096; r += 256) {
                float4 v = *(const float4*)(hT + hoff + r * 4);
                int k = r >> 2, b4 = r & 3;
                *(float4*)(h_s + k * HROW + b4 * 4) = v;
            }
        }
        __syncthreads();

        // --- prefetch gi + hprev (hidden under the mainloop) ---
        float gir = 0.f, giz = 0.f, gin = 0.f, hprev = 0.f;
        if (tid < 128) {
            const size_t gb = ((size_t)b_c * SDIM + t) * 3072 + col_c;
            gir = __ldg(gi + gb);
            giz = __ldg(gi + gb + 1024);
            gin = __ldg(gi + gb + 2048);
            hprev = h_s[col_c * HROW + b_c];
        }

        // --- mainloop: 6 cols x 8 f32x2 x 16 k-iters ---
        unsigned long long acc[6][8];
#pragma unroll
        for (int c = 0; c < 6; c++)
#pragma unroll
            for (int p = 0; p < 8; p++) acc[c][p] = 0ull;

#pragma unroll 4
        for (int i = 0; i < 16; i++) {
            const int k = ks + (i << 6);
            const float* hrow = h_s + k * HROW;
            unsigned long long hp[8];
            {
                ulonglong2 u0 = *(const ulonglong2*)(hrow);
                ulonglong2 u1 = *(const ulonglong2*)(hrow + 4);
                ulonglong2 u2 = *(const ulonglong2*)(hrow + 8);
                ulonglong2 u3 = *(const ulonglong2*)(hrow + 12);
                hp[0] = u0.x; hp[1] = u0.y; hp[2] = u1.x; hp[3] = u1.y;
                hp[4] = u2.x; hp[5] = u2.y; hp[6] = u3.x; hp[7] = u3.y;
            }
#pragma unroll
            for (int c = 0; c < 6; c++) {
                unsigned long long wd = dup2(wc[c][i << 6]);
#pragma unroll
                for (int p = 0; p < 8; p++) FMA2(acc[c][p], wd, hp[p]);
            }
        }

        // --- 64-way k reduction in two halves (dump reuses h_s) ---
        unsigned long long* dmp = (unsigned long long*)h_s;
#pragma unroll
        for (int hh = 0; hh < 2; hh++) {
            __syncthreads();   // h_s / previous dump fully consumed
#pragma unroll
            for (int g = 0; g < 3; g++)
#pragma unroll
                for (int p = 0; p < 8; p++)
                    dmp[tid * 25 + g * 8 + p] = acc[hh * 3 + g][p];
            __syncthreads();
            if (tid < 96) {
                int cgo = tid / 24, s = tid % 24;
                unsigned long long sum = dmp[(cgo * 64) * 25 + s];
#pragma unroll 8
                for (int q = 1; q < 64; q++)
                    ADD2(sum, dmp[(cgo * 64 + q) * 25 + s]);
                red_s[hh * 96 + cgo * 24 + s] = sum;
            }
        }
        __syncthreads();

        // --- combine + activations + write ---
        if (tid < 128) {
            int cgc = jl_c >> 1, hh = jl_c & 1, p = b_c >> 1, lane = b_c & 1;
            const float* rf = (const float*)red_s;
            int base = (hh * 96 + cgc * 24) * 2 + p * 2 + lane;
            float ar = rf[base];
            float az = rf[base + 16];   // (g=1)*8*2
            float an = rf[base + 32];   // (g=2)*8*2

            float r = 1.f / (1.f + expf(-(gir + ar + bh0)));
            float z = 1.f / (1.f + expf(-(giz + az + bh1)));
            float n = tanhf(gin + r * (an + bh2));
            float hnew = (1.f - z) * n + z * hprev;

            rnn[((size_t)b_c * SDIM + t) * HDIM + col_c] = hnew;
            hT[(t & 1) * (HDIM * BDIM) + col_c * BDIM + b_c] = hnew;
        }

        gsync();   // h_T[t] visible chip-wide before anyone stages step t+1
    }
}

// ---------------------------------------------------------------------------
// hidden = rnn[:, S-1, :]; attn = ones (softmax over a size-1 axis).
// d_out layout: [output B*S*I][hidden B*H][attn B*S]
// ---------------------------------------------------------------------------
__global__ void finalize_kernel(const float* __restrict__ rnn, float* __restrict__ out)
{
    const size_t OUT_ELEMS = (size_t)BDIM * SDIM * IDIM;
    int i = blockIdx.x * blockDim.x + threadIdx.x;
    if (i < BDIM * HDIM) {
        int b = i >> 10, h = i & 1023;
        out[OUT_ELEMS + i] = rnn[((size_t)b * SDIM + (SDIM - 1)) * HDIM + h];
    }
    if (i < BDIM * SDIM) {
        out[OUT_ELEMS + BDIM * HDIM + i] = 1.0f;
    }
}

extern "C" void kernel_launch(void* const* d_in, const int* in_sizes, int n_in,
                              void* d_out, int out_size)
{
    const float* x    = (const float*)d_in[0];
    // d_in[1..4] = attn MLP -> algebraically dead (softmax over size-1 axis == 1)
    const float* w_ih = (const float*)d_in[5];
    const float* w_hh = (const float*)d_in[6];
    const float* b_ih = (const float*)d_in[7];
    const float* b_hh = (const float*)d_in[8];
    const float* fc_w = (const float*)d_in[9];
    const float* fc_b = (const float*)d_in[10];
    float* out = (float*)d_out;

    float *gi = nullptr, *rnn = nullptr, *hT = nullptr;
    cudaGetSymbolAddress((void**)&gi, g_gi);
    cudaGetSymbolAddress((void**)&rnn, g_rnn);
    cudaGetSymbolAddress((void**)&hT, g_hT);

    const int smemB = (SM_W + SM_H) * (int)sizeof(float) + SM_RED * (int)sizeof(unsigned long long);
    static bool attr_done = false;
    if (!attr_done) {
        cudaFuncSetAttribute(gru_persistent, cudaFuncAttributeMaxDynamicSharedMemorySize, smemB);
        attr_done = true;
    }

    // gi = x @ w_ih^T + b_ih   (M=32768, N=3072, K=1024)
    {
        dim3 grid(3 * HDIM / 128, BDIM * SDIM / 128);
        sgemm_nt<<<grid, 256>>>(x, w_ih, b_ih, gi, BDIM * SDIM, 3 * HDIM, IDIM);
    }

    // GRU: one persistent kernel, 2048 steps, software grid barrier
    gru_persistent<<<NBLK, 256, smemB>>>(gi, w_hh, b_hh, rnn, hT);

    // output = rnn_out @ fc_w^T + fc_b   (M=32768, N=1024, K=1024)
    {
        dim3 grid(IDIM / 128, BDIM * SDIM / 128);
        sgemm_nt<<<grid, 256>>>(rnn, fc_w, fc_b, out, BDIM * SDIM, IDIM, HDIM);
    }

    finalize_kernel<<<192, 256>>>(rnn, out);
}